// round 8
// baseline (speedup 1.0000x reference)
#include <cuda_runtime.h>

// GCN: out = spmm(w, relu(spmm(w, x@W1^T) + b1) @ W2^T) + b2
// using the commutation spmm(h)@W^T == spmm(h@W^T).
//
// Round 8: GEMMs rewritten with packed fp32 FMA (PTX fma.rn.f32x2 -> FFMA2,
// 2x fp32 rate on sm_103a; ptxas never auto-fuses). 8x8 thread tile so
// MACs/smem-float = 4 (balanced against 128 lane-MACs/cyc/SM vs 32 floats/cyc
// crossbar). W tile k-major -> column pairs load as ulonglong2 (native f32x2
// operands); X tile row-major -> a-side is 1-cyc scalar broadcasts + dup MOVs
// (hidden: 50 issue slots < 64 FMA-pipe cycles per warp per k).

#define NMAX 100000
#define EMAX 1600000

__device__ int   g_is64;
__device__ float g_deg[NMAX];            // degree, then dinv (in place)
__device__ int   g_cnt[NMAX];
__device__ int   g_rowptr[NMAX + 1];
__device__ int   g_cursor[NMAX];
__device__ int   g_colp[EMAX];
__device__ float g_wp[EMAX];
__device__ __align__(16) float g_y1[(size_t)NMAX * 128];
__device__ __align__(16) float g_h [(size_t)NMAX * 128];
__device__ __align__(16) float g_y2[(size_t)NMAX * 40];

typedef unsigned long long u64;

__device__ __forceinline__ u64 dup_f32x2(float a) {
    u64 r; asm("mov.b64 %0, {%1, %1};" : "=l"(r) : "f"(a)); return r;
}
__device__ __forceinline__ void fma_f32x2(u64& d, u64 a, u64 b) {
    asm("fma.rn.f32x2 %0, %1, %2, %3;" : "=l"(d) : "l"(a), "l"(b), "l"(d));
}
__device__ __forceinline__ void unpack_f32x2(float& lo, float& hi, u64 v) {
    asm("mov.b64 {%0, %1}, %2;" : "=f"(lo), "=f"(hi) : "l"(v));
}

// read edge index e from row (part==0) or col (part==1) stream
__device__ __forceinline__ int edge_at(const void* ei, int E, int part, int e,
                                       int is64) {
    if (is64) return (int)((const long long*)ei)[(size_t)part * E + e];
    return ((const int*)ei)[(size_t)part * E + e];
}

// -------------------------------------------------- dtype detector (1 thr)
__global__ void k_detect(const void* ei, int E) {
    const long long* p = (const long long*)ei;
    int ok = 1;
    int m = (E < 8) ? E : 8;
    for (int i = 0; i < m; i++) {
        long long v = p[i];
        if (v < 0 || v >= NMAX) ok = 0;
    }
    g_is64 = ok;
}

// ---------------------------------------------------------------- zero
__global__ void k_zero(int n) {
    int i = blockIdx.x * blockDim.x + threadIdx.x;
    if (i < n) { g_deg[i] = 0.0f; g_cnt[i] = 0; }
}

// ------------------------------------------------------- degree + count
__global__ void k_deg_count(const void* __restrict__ ei,
                            const float* __restrict__ cv, int E) {
    int e = blockIdx.x * blockDim.x + threadIdx.x;
    if (e >= E) return;
    int is64 = g_is64;
    int r = edge_at(ei, E, 0, e, is64);
    atomicAdd(&g_deg[r], cv[e]);
    atomicAdd(&g_cnt[r], 1);
}

// ----------------------------------------------------------------- dinv
__global__ void k_dinv(int n) {
    int i = blockIdx.x * blockDim.x + threadIdx.x;
    if (i < n) {
        float d = g_deg[i];
        g_deg[i] = (d > 0.0f) ? rsqrtf(d) : 0.0f;
    }
}

// -------------------------------------------- single-block exclusive scan
__global__ void k_scan(int n) {
    __shared__ int warp_sums[32];
    __shared__ int carry_s;
    int tid = threadIdx.x;
    if (tid == 0) carry_s = 0;
    __syncthreads();
    int lane = tid & 31, w = tid >> 5;
    for (int base = 0; base < n; base += blockDim.x) {
        int i = base + tid;
        int v = (i < n) ? g_cnt[i] : 0;
        int s = v;
        #pragma unroll
        for (int o = 1; o < 32; o <<= 1) {
            int t = __shfl_up_sync(0xFFFFFFFFu, s, o);
            if (lane >= o) s += t;
        }
        if (lane == 31) warp_sums[w] = s;
        __syncthreads();
        if (w == 0) {
            int ws = warp_sums[lane];
            #pragma unroll
            for (int o = 1; o < 32; o <<= 1) {
                int t = __shfl_up_sync(0xFFFFFFFFu, ws, o);
                if (lane >= o) ws += t;
            }
            warp_sums[lane] = ws;
        }
        __syncthreads();
        int incl = s + (w > 0 ? warp_sums[w - 1] : 0) + carry_s;
        int excl = incl - v;
        if (i < n) { g_rowptr[i] = excl; g_cursor[i] = excl; }
        __syncthreads();
        if (tid == blockDim.x - 1) carry_s = incl;
        __syncthreads();
    }
    if (tid == 0) g_rowptr[n] = carry_s;
}

// -------------------------------------------------------- CSR scatter + w
__global__ void k_scatter(const void* __restrict__ ei,
                          const float* __restrict__ cv, int E) {
    int e = blockIdx.x * blockDim.x + threadIdx.x;
    if (e >= E) return;
    int is64 = g_is64;
    int r = edge_at(ei, E, 0, e, is64);
    int c = edge_at(ei, E, 1, e, is64);
    float wv = g_deg[r] * cv[e] * g_deg[c];
    int pos = atomicAdd(&g_cursor[r], 1);
    g_colp[pos] = c;
    g_wp[pos]   = wv;
}

// ------------------------------------------------ dense GEMM with f32x2
// Y[n, c] = sum_k X[n,k] * W[c,k].  Node tile 64, col tile CT (128 or 64).
// Threads: (CT/8) x 8 = TX*8. Thread tile 8 rows x 8 cols (4 col-pairs).
// xs: row-major [64][128] (scalar broadcast reads).  wsT: k-major chunked
// [16][CT+4] so col pairs read as ulonglong2 (native f32x2 operands).
// LAYER==1: X = Xin, Y = g_y1 (stride 128). LAYER==2: X = g_h, Y = g_y2.
template <int CT, int LAYER>
__global__ void k_gemm2x(const float* __restrict__ Xin,
                         const float* __restrict__ W, int N, int Hreal) {
    constexpr int TX = CT / 8;          // 16 or 8
    constexpr int NTHR = TX * 8;        // 128 or 64
    constexpr int SW = CT + 4;          // 132 or 68 (both keep 16B rows)
    __shared__ __align__(16) float xs[64 * 128];
    __shared__ __align__(16) float wsT[16 * SW];

    const float* X = (LAYER == 1) ? Xin : (const float*)g_h;
    float*       Y = (LAYER == 1) ? g_y1 : g_y2;

    int tid = threadIdx.x;
    int nb = blockIdx.x * 64;
    int tx = tid % TX, ty = tid / TX;

    // fill x tile (row-major, float4, coalesced)
    {
        const float4* Xv = (const float4*)(X + (size_t)nb * 128);
        float4* xv = (float4*)xs;
        for (int i = tid; i < 64 * 32; i += NTHR) {
            int n = i >> 5;
            xv[i] = (nb + n < N) ? Xv[i]
                                 : make_float4(0.f, 0.f, 0.f, 0.f);
        }
    }

    u64 acc[8][4];
    #pragma unroll
    for (int i = 0; i < 8; i++)
        #pragma unroll
        for (int j = 0; j < 4; j++) acc[i][j] = 0ull;

    const float* xrow = xs + (ty * 8) * 128;

    for (int kb = 0; kb < 128; kb += 16) {
        __syncthreads();
        // fill W chunk transposed: wsT[kk][c] = W[c][kb+kk]
        for (int i = tid; i < CT * 16; i += NTHR) {
            int c = i >> 4, kk = i & 15;       // read W[c][kb+kk] coalesced
            wsT[kk * SW + c] = (c < Hreal) ? W[(size_t)c * 128 + kb + kk] : 0.0f;
        }
        __syncthreads();

        #pragma unroll
        for (int kk = 0; kk < 16; kk++) {
            const ulonglong2* wp =
                (const ulonglong2*)&wsT[kk * SW + tx * 8];
            ulonglong2 b01 = wp[0];
            ulonglong2 b23 = wp[1];
            #pragma unroll
            for (int i = 0; i < 8; i++) {
                u64 a2 = dup_f32x2(xrow[i * 128 + kb + kk]);
                fma_f32x2(acc[i][0], a2, b01.x);
                fma_f32x2(acc[i][1], a2, b01.y);
                fma_f32x2(acc[i][2], a2, b23.x);
                fma_f32x2(acc[i][3], a2, b23.y);
            }
        }
    }

    #pragma unroll
    for (int i = 0; i < 8; i++) {
        int n = nb + ty * 8 + i;
        if (n >= N) break;
        float* yrow = Y + (size_t)n * Hreal;
        #pragma unroll
        for (int j = 0; j < 4; j++) {
            int c = tx * 8 + 2 * j;
            float lo, hi;
            unpack_f32x2(lo, hi, acc[i][j]);
            if (c < Hreal)     yrow[c]     = lo;
            if (c + 1 < Hreal) yrow[c + 1] = hi;
        }
    }
}

// ---------------------------------------- CSR SpMM, 128 feats, bias+relu
// reads g_y1, writes g_h
__global__ void k_spmm128(const float* __restrict__ bias, int N) {
    int wid = threadIdx.x >> 5, lane = threadIdx.x & 31;
    int r = blockIdx.x * 8 + wid;
    if (r >= N) return;
    const float4* feat = (const float4*)g_y1;
    int e0 = g_rowptr[r], e1 = g_rowptr[r + 1];
    float4 acc = make_float4(0.f, 0.f, 0.f, 0.f);
    for (int e = e0; e < e1; e++) {
        int c = g_colp[e];
        float wv = g_wp[e];
        float4 v = feat[(size_t)c * 32 + lane];
        acc.x = fmaf(wv, v.x, acc.x);
        acc.y = fmaf(wv, v.y, acc.y);
        acc.z = fmaf(wv, v.z, acc.z);
        acc.w = fmaf(wv, v.w, acc.w);
    }
    float4 b = ((const float4*)bias)[lane];
    acc.x = fmaxf(acc.x + b.x, 0.f);
    acc.y = fmaxf(acc.y + b.y, 0.f);
    acc.z = fmaxf(acc.z + b.z, 0.f);
    acc.w = fmaxf(acc.w + b.w, 0.f);
    ((float4*)g_h)[(size_t)r * 32 + lane] = acc;
}

// -------------------------------------------- CSR SpMM, 40 feats, + bias
// reads g_y2, writes out
__global__ void k_spmm40(const float* __restrict__ bias,
                         float* __restrict__ out, int N) {
    int wid = threadIdx.x >> 5, lane = threadIdx.x & 31;
    int r = blockIdx.x * 8 + wid;
    if (r >= N) return;
    int e0 = g_rowptr[r], e1 = g_rowptr[r + 1];
    float a0 = 0.f, a1 = 0.f;
    for (int e = e0; e < e1; e++) {
        int c = g_colp[e];
        float wv = g_wp[e];
        const float* f = g_y2 + (size_t)c * 40;
        a0 = fmaf(wv, f[lane], a0);
        if (lane < 8) a1 = fmaf(wv, f[32 + lane], a1);
    }
    out[(size_t)r * 40 + lane] = a0 + bias[lane];
    if (lane < 8) out[(size_t)r * 40 + 32 + lane] = a1 + bias[32 + lane];
}

// ----------------------------------------------------------------- host
extern "C" void kernel_launch(void* const* d_in, const int* in_sizes, int n_in,
                              void* d_out, int out_size) {
    const float* x  = (const float*)d_in[0];
    const void*  ei = d_in[1];                 // int32 or int64, detected
    const float* cv = (const float*)d_in[2];
    const float* W1 = (const float*)d_in[3];
    const float* b1 = (const float*)d_in[4];
    const float* W2 = (const float*)d_in[5];
    const float* b2 = (const float*)d_in[6];
    float* out = (float*)d_out;

    int N = in_sizes[0] / 128;
    int E = in_sizes[2];

    int gn = (N + 255) / 256;
    int ge = (E + 255) / 256;

    k_detect<<<1, 1>>>(ei, E);
    k_zero<<<gn, 256>>>(N);
    k_deg_count<<<ge, 256>>>(ei, cv, E);
    k_dinv<<<gn, 256>>>(N);
    k_scan<<<1, 1024>>>(N);
    k_scatter<<<ge, 256>>>(ei, cv, E);

    int gb = (N + 63) / 64;

    // GEMM1: y1 = x @ W1^T, 128 cols
    k_gemm2x<128, 1><<<gb, 128>>>(x, W1, N, 128);

    // SpMM1 + bias + relu -> h
    k_spmm128<<<(N + 7) / 8, 256>>>(b1, N);

    // GEMM2: y2 = h @ W2^T, 40 cols (padded to 64 in-kernel)
    k_gemm2x<64, 2><<<gb, 64>>>(nullptr, W2, N, 40);

    // SpMM2 + bias -> out
    k_spmm40<<<(N + 7) / 8, 256>>>(b2, out, N);
}

// round 9
// speedup vs baseline: 1.0808x; 1.0808x over previous
#include <cuda_runtime.h>

// GCN: out = spmm(w, relu(spmm(w, x@W1^T) + b1) @ W2^T) + b2
// using the commutation spmm(h)@W^T == spmm(h@W^T).
//
// Round 9:
//  - GEMM reverted to the round-7 scalar-FFMA form (f32x2 regressed).
//  - CSR build chain forked onto a second stream, joined before spmm128:
//    GEMM1 depends only on (x, W1), so the ~65us build hides behind it.
//  - detect merged into k_zero; CSR stored interleaved as int2{col,w_bits}
//    (one 8B store in scatter, one 8B load per edge in the spmm loops).

#define NMAX 100000
#define EMAX 1600000

__device__ int   g_is64;
__device__ float g_deg[NMAX];            // degree, then dinv (in place)
__device__ int   g_cnt[NMAX];
__device__ int   g_rowptr[NMAX + 1];
__device__ int   g_cursor[NMAX];
__device__ __align__(16) int2  g_cw[EMAX];       // {col, __float_as_int(w)}
__device__ __align__(16) float g_y1[(size_t)NMAX * 128];
__device__ __align__(16) float g_h [(size_t)NMAX * 128];
__device__ __align__(16) float g_y2[(size_t)NMAX * 40];

// read edge index e from row (part==0) or col (part==1) stream
__device__ __forceinline__ int edge_at(const void* ei, int E, int part, int e,
                                       int is64) {
    if (is64) return (int)((const long long*)ei)[(size_t)part * E + e];
    return ((const int*)ei)[(size_t)part * E + e];
}

// ------------------------------------------ zero + dtype detect (merged)
__global__ void k_zero(const void* ei, int E, int n) {
    int i = blockIdx.x * blockDim.x + threadIdx.x;
    if (i < n) { g_deg[i] = 0.0f; g_cnt[i] = 0; }
    if (i == 0) {
        // int64 indices are < NMAX; int32 pairs read as int64 are >= 2^32
        // unless the high half is exactly 0 (prob ~1e-5 each; check 8).
        const long long* p = (const long long*)ei;
        int ok = 1;
        int m = (E < 8) ? E : 8;
        for (int j = 0; j < m; j++) {
            long long v = p[j];
            if (v < 0 || v >= NMAX) ok = 0;
        }
        g_is64 = ok;
    }
}

// ------------------------------------------------------- degree + count
__global__ void k_deg_count(const void* __restrict__ ei,
                            const float* __restrict__ cv, int E) {
    int e = blockIdx.x * blockDim.x + threadIdx.x;
    if (e >= E) return;
    int is64 = g_is64;
    int r = edge_at(ei, E, 0, e, is64);
    atomicAdd(&g_deg[r], cv[e]);
    atomicAdd(&g_cnt[r], 1);
}

// ----------------------------------------------------------------- dinv
__global__ void k_dinv(int n) {
    int i = blockIdx.x * blockDim.x + threadIdx.x;
    if (i < n) {
        float d = g_deg[i];
        g_deg[i] = (d > 0.0f) ? rsqrtf(d) : 0.0f;
    }
}

// -------------------------------------------- single-block exclusive scan
__global__ void k_scan(int n) {
    __shared__ int warp_sums[32];
    __shared__ int carry_s;
    int tid = threadIdx.x;
    if (tid == 0) carry_s = 0;
    __syncthreads();
    int lane = tid & 31, w = tid >> 5;
    for (int base = 0; base < n; base += blockDim.x) {
        int i = base + tid;
        int v = (i < n) ? g_cnt[i] : 0;
        int s = v;
        #pragma unroll
        for (int o = 1; o < 32; o <<= 1) {
            int t = __shfl_up_sync(0xFFFFFFFFu, s, o);
            if (lane >= o) s += t;
        }
        if (lane == 31) warp_sums[w] = s;
        __syncthreads();
        if (w == 0) {
            int ws = warp_sums[lane];
            #pragma unroll
            for (int o = 1; o < 32; o <<= 1) {
                int t = __shfl_up_sync(0xFFFFFFFFu, ws, o);
                if (lane >= o) ws += t;
            }
            warp_sums[lane] = ws;
        }
        __syncthreads();
        int incl = s + (w > 0 ? warp_sums[w - 1] : 0) + carry_s;
        int excl = incl - v;
        if (i < n) { g_rowptr[i] = excl; g_cursor[i] = excl; }
        __syncthreads();
        if (tid == blockDim.x - 1) carry_s = incl;
        __syncthreads();
    }
    if (tid == 0) g_rowptr[n] = carry_s;
}

// -------------------------------------------------------- CSR scatter + w
__global__ void k_scatter(const void* __restrict__ ei,
                          const float* __restrict__ cv, int E) {
    int e = blockIdx.x * blockDim.x + threadIdx.x;
    if (e >= E) return;
    int is64 = g_is64;
    int r = edge_at(ei, E, 0, e, is64);
    int c = edge_at(ei, E, 1, e, is64);
    float wv = g_deg[r] * cv[e] * g_deg[c];
    int pos = atomicAdd(&g_cursor[r], 1);
    g_cw[pos] = make_int2(c, __float_as_int(wv));
}

// ---------------------------------------------------------- dense GEMM
// Y[n, c] = sum_k X[n,k] * W[c,k].
// Block: 64 nodes, 256 threads (8 warps). Warp handles 8 nodes; lane handles
// cols lane + 32*j, j < HT. W tile loaded in k-chunks of 16 (stride 17 ->
// conflict-free: gcd(17,32)=1). x tile stride 128 is fine: reads are
// lane-invariant broadcasts. Static smem: 32KB + HT*32*17*4 <= 40.7KB.
// LAYER==1: X = Xin param, Y = g_y1. LAYER==2: X = g_h, Y = g_y2.
template <int HT, int LAYER>
__global__ void k_gemm(const float* __restrict__ Xin,
                       const float* __restrict__ W, int N, int Hreal) {
    __shared__ float xs[64 * 128];
    __shared__ float ws[HT * 32 * 17];
    const float* X = (LAYER == 1) ? Xin : (const float*)g_h;
    float*       Y = (LAYER == 1) ? g_y1 : g_y2;

    int tid = threadIdx.x;
    int nb = blockIdx.x * 64;

    for (int i = tid; i < 64 * 128; i += 256) {
        int n = i >> 7;
        xs[i] = (nb + n < N) ? X[(size_t)nb * 128 + i] : 0.0f;
    }

    int lane = tid & 31, wid = tid >> 5;
    float acc[8][HT];
    #pragma unroll
    for (int i = 0; i < 8; i++)
        #pragma unroll
        for (int j = 0; j < HT; j++) acc[i][j] = 0.0f;

    for (int kb = 0; kb < 128; kb += 16) {
        __syncthreads();
        for (int i = tid; i < HT * 32 * 16; i += 256) {
            int hh = i >> 4, kk = i & 15;
            ws[hh * 17 + kk] = (hh < Hreal) ? W[(size_t)hh * 128 + kb + kk] : 0.0f;
        }
        __syncthreads();

        #pragma unroll
        for (int kk = 0; kk < 16; kk++) {
            float wf[HT];
            #pragma unroll
            for (int j = 0; j < HT; j++) wf[j] = ws[(lane + 32 * j) * 17 + kk];
            #pragma unroll
            for (int i = 0; i < 8; i++) {
                float xf = xs[(wid * 8 + i) * 128 + kb + kk];
                #pragma unroll
                for (int j = 0; j < HT; j++)
                    acc[i][j] = fmaf(xf, wf[j], acc[i][j]);
            }
        }
    }

    #pragma unroll
    for (int i = 0; i < 8; i++) {
        int n = nb + wid * 8 + i;
        if (n < N) {
            #pragma unroll
            for (int j = 0; j < HT; j++) {
                int c = lane + 32 * j;
                if (c < Hreal) Y[(size_t)n * Hreal + c] = acc[i][j];
            }
        }
    }
}

// ---------------------------------------- CSR SpMM, 128 feats, bias+relu
// reads g_y1, writes g_h
__global__ void k_spmm128(const float* __restrict__ bias, int N) {
    int wid = threadIdx.x >> 5, lane = threadIdx.x & 31;
    int r = blockIdx.x * 8 + wid;
    if (r >= N) return;
    const float4* feat = (const float4*)g_y1;
    int e0 = g_rowptr[r], e1 = g_rowptr[r + 1];
    float4 acc = make_float4(0.f, 0.f, 0.f, 0.f);
    for (int e = e0; e < e1; e++) {
        int2 cw = g_cw[e];
        float wv = __int_as_float(cw.y);
        float4 v = feat[(size_t)cw.x * 32 + lane];
        acc.x = fmaf(wv, v.x, acc.x);
        acc.y = fmaf(wv, v.y, acc.y);
        acc.z = fmaf(wv, v.z, acc.z);
        acc.w = fmaf(wv, v.w, acc.w);
    }
    float4 b = ((const float4*)bias)[lane];
    acc.x = fmaxf(acc.x + b.x, 0.f);
    acc.y = fmaxf(acc.y + b.y, 0.f);
    acc.z = fmaxf(acc.z + b.z, 0.f);
    acc.w = fmaxf(acc.w + b.w, 0.f);
    ((float4*)g_h)[(size_t)r * 32 + lane] = acc;
}

// -------------------------------------------- CSR SpMM, 40 feats, + bias
// reads g_y2, writes out
__global__ void k_spmm40(const float* __restrict__ bias,
                         float* __restrict__ out, int N) {
    int wid = threadIdx.x >> 5, lane = threadIdx.x & 31;
    int r = blockIdx.x * 8 + wid;
    if (r >= N) return;
    int e0 = g_rowptr[r], e1 = g_rowptr[r + 1];
    float a0 = 0.f, a1 = 0.f;
    for (int e = e0; e < e1; e++) {
        int2 cw = g_cw[e];
        float wv = __int_as_float(cw.y);
        const float* f = g_y2 + (size_t)cw.x * 40;
        a0 = fmaf(wv, f[lane], a0);
        if (lane < 8) a1 = fmaf(wv, f[32 + lane], a1);
    }
    out[(size_t)r * 40 + lane] = a0 + bias[lane];
    if (lane < 8) out[(size_t)r * 40 + 32 + lane] = a1 + bias[32 + lane];
}

// ----------------------------------------------------------------- host
extern "C" void kernel_launch(void* const* d_in, const int* in_sizes, int n_in,
                              void* d_out, int out_size) {
    const float* x  = (const float*)d_in[0];
    const void*  ei = d_in[1];                 // int32 or int64, detected
    const float* cv = (const float*)d_in[2];
    const float* W1 = (const float*)d_in[3];
    const float* b1 = (const float*)d_in[4];
    const float* W2 = (const float*)d_in[5];
    const float* b2 = (const float*)d_in[6];
    float* out = (float*)d_out;

    int N = in_sizes[0] / 128;
    int E = in_sizes[2];

    // Side stream + events, created once on the first (non-capturing)
    // correctness call; reused on the capture call. No device allocation.
    static cudaStream_t s1 = nullptr;
    static cudaEvent_t ev_fork = nullptr, ev_join = nullptr;
    if (s1 == nullptr) {
        cudaStreamCreateWithFlags(&s1, cudaStreamNonBlocking);
        cudaEventCreateWithFlags(&ev_fork, cudaEventDisableTiming);
        cudaEventCreateWithFlags(&ev_join, cudaEventDisableTiming);
    }

    int gn = (N + 255) / 256;
    int ge = (E + 255) / 256;
    int gb = (N + 63) / 64;

    // Fork: CSR build chain on s1, concurrent with GEMM1 on the main stream.
    cudaEventRecord(ev_fork, 0);
    cudaStreamWaitEvent(s1, ev_fork, 0);

    k_zero     <<<gn, 256, 0, s1>>>(ei, E, N);
    k_deg_count<<<ge, 256, 0, s1>>>(ei, cv, E);
    k_dinv     <<<gn, 256, 0, s1>>>(N);
    k_scan     <<<1, 1024, 0, s1>>>(N);
    k_scatter  <<<ge, 256, 0, s1>>>(ei, cv, E);
    cudaEventRecord(ev_join, s1);

    // GEMM1 on main stream: y1 = x @ W1^T, 128 cols (independent of CSR).
    k_gemm<4, 1><<<gb, 256>>>(x, W1, N, 128);

    // Join: spmm128 needs both y1 and the CSR.
    cudaStreamWaitEvent(0, ev_join, 0);

    // SpMM1 + bias + relu -> h
    k_spmm128<<<(N + 7) / 8, 256>>>(b1, N);

    // GEMM2: y2 = h @ W2^T, 40 cols (padded to 64 in-kernel)
    k_gemm<2, 2><<<gb, 256>>>(nullptr, W2, N, 40);

    // SpMM2 + bias -> out
    k_spmm40<<<(N + 7) / 8, 256>>>(b2, out, N);
}

// round 10
// speedup vs baseline: 1.3033x; 1.2058x over previous
#include <cuda_runtime.h>

// GCN: out = spmm(w, relu(spmm(w, x@W1^T) + b1) @ W2^T) + b2
// using the commutation spmm(h)@W^T == spmm(h@W^T).
//
// Round 10:
//  - single-block scan (measured 96us, grid=1 latency-bound) replaced by a
//    3-kernel multi-block scan (reduce / scan-sums / propagate), ~15us.
//  - dinv fused into scan pass 1 (one fewer launch on the side stream).
//  - CSR build chain forked on a 2nd stream, hidden behind GEMM1.

#define NMAX 100000
#define EMAX 1600000
#define SCAN_CHUNK 1024                       // elems per scan block
#define SCAN_NB ((NMAX + SCAN_CHUNK - 1) / SCAN_CHUNK)   // 98 <= 128

__device__ int   g_is64;
__device__ __align__(16) float g_deg[NMAX];   // degree, then dinv (in place)
__device__ __align__(16) int   g_cnt[NMAX];
__device__ int   g_rowptr[NMAX + 1];
__device__ int   g_cursor[NMAX];
__device__ int   g_bsum[128];
__device__ int   g_boff[128];
__device__ __align__(16) int2  g_cw[EMAX];    // {col, __float_as_int(w)}
__device__ __align__(16) float g_y1[(size_t)NMAX * 128];
__device__ __align__(16) float g_h [(size_t)NMAX * 128];
__device__ __align__(16) float g_y2[(size_t)NMAX * 40];

// read edge index e from row (part==0) or col (part==1) stream
__device__ __forceinline__ int edge_at(const void* ei, int E, int part, int e,
                                       int is64) {
    if (is64) return (int)((const long long*)ei)[(size_t)part * E + e];
    return ((const int*)ei)[(size_t)part * E + e];
}

// ------------------------------------------ zero + dtype detect (merged)
__global__ void k_zero(const void* ei, int E, int n) {
    int i = blockIdx.x * blockDim.x + threadIdx.x;
    if (i < n) { g_deg[i] = 0.0f; g_cnt[i] = 0; }
    if (i == 0) {
        // int64 indices are < NMAX; int32 pairs read as int64 are >= 2^32
        // unless the high half is exactly 0 (prob ~1e-5 each; check 8).
        const long long* p = (const long long*)ei;
        int ok = 1;
        int m = (E < 8) ? E : 8;
        for (int j = 0; j < m; j++) {
            long long v = p[j];
            if (v < 0 || v >= NMAX) ok = 0;
        }
        g_is64 = ok;
    }
}

// ------------------------------------------------------- degree + count
__global__ void k_deg_count(const void* __restrict__ ei,
                            const float* __restrict__ cv, int E) {
    int e = blockIdx.x * blockDim.x + threadIdx.x;
    if (e >= E) return;
    int is64 = g_is64;
    int r = edge_at(ei, E, 0, e, is64);
    atomicAdd(&g_deg[r], cv[e]);
    atomicAdd(&g_cnt[r], 1);
}

// ------------------------------------- scan pass 1: block sums (+ dinv)
// 256 threads/block, 4 elems/thread -> 1024 elems/block.
__global__ void k_scan1(int n) {
    __shared__ int wsum[8];
    int b = blockIdx.x, t = threadIdx.x;
    int base = b * SCAN_CHUNK + t * 4;

    int4 v = make_int4(0, 0, 0, 0);
    if (base + 3 < n)      v = *(const int4*)&g_cnt[base];
    else if (base < n) {
        v.x = g_cnt[base];
        if (base + 1 < n) v.y = g_cnt[base + 1];
        if (base + 2 < n) v.z = g_cnt[base + 2];
    }
    int s = v.x + v.y + v.z + v.w;

    int lane = t & 31, w = t >> 5;
    int inc = s;
    #pragma unroll
    for (int o = 1; o < 32; o <<= 1) {
        int tv = __shfl_up_sync(0xFFFFFFFFu, inc, o);
        if (lane >= o) inc += tv;
    }
    if (lane == 31) wsum[w] = inc;
    __syncthreads();
    if (t == 0) {
        int tot = 0;
        #pragma unroll
        for (int j = 0; j < 8; j++) tot += wsum[j];
        g_bsum[b] = tot;
    }

    // fused dinv over the same range
    if (base + 3 < n) {
        float4 d = *(const float4*)&g_deg[base];
        d.x = (d.x > 0.f) ? rsqrtf(d.x) : 0.f;
        d.y = (d.y > 0.f) ? rsqrtf(d.y) : 0.f;
        d.z = (d.z > 0.f) ? rsqrtf(d.z) : 0.f;
        d.w = (d.w > 0.f) ? rsqrtf(d.w) : 0.f;
        *(float4*)&g_deg[base] = d;
    } else {
        for (int j = 0; j < 4 && base + j < n; j++) {
            float d = g_deg[base + j];
            g_deg[base + j] = (d > 0.f) ? rsqrtf(d) : 0.f;
        }
    }
}

// ---------------------------- scan pass 2: exclusive scan of block sums
// one block, 128 threads, nb <= 128.
__global__ void k_scan2(int nb, int n) {
    __shared__ int wtot[4];
    int t = threadIdx.x;
    int v = (t < nb) ? g_bsum[t] : 0;
    int lane = t & 31, w = t >> 5;
    int inc = v;
    #pragma unroll
    for (int o = 1; o < 32; o <<= 1) {
        int tv = __shfl_up_sync(0xFFFFFFFFu, inc, o);
        if (lane >= o) inc += tv;
    }
    if (lane == 31) wtot[w] = inc;
    __syncthreads();
    int woff = 0;
    #pragma unroll
    for (int j = 0; j < 4; j++) if (j < w) woff += wtot[j];
    int excl = woff + inc - v;
    if (t < nb) g_boff[t] = excl;
    if (t == 127) g_rowptr[n] = woff + inc;   // grand total
}

// ------------------------- scan pass 3: propagate, write rowptr + cursor
__global__ void k_scan3(int n) {
    __shared__ int wsum[8];
    int b = blockIdx.x, t = threadIdx.x;
    int base = b * SCAN_CHUNK + t * 4;

    int4 v = make_int4(0, 0, 0, 0);
    if (base + 3 < n)      v = *(const int4*)&g_cnt[base];
    else if (base < n) {
        v.x = g_cnt[base];
        if (base + 1 < n) v.y = g_cnt[base + 1];
        if (base + 2 < n) v.z = g_cnt[base + 2];
    }
    int s = v.x + v.y + v.z + v.w;

    int lane = t & 31, w = t >> 5;
    int inc = s;
    #pragma unroll
    for (int o = 1; o < 32; o <<= 1) {
        int tv = __shfl_up_sync(0xFFFFFFFFu, inc, o);
        if (lane >= o) inc += tv;
    }
    if (lane == 31) wsum[w] = inc;
    __syncthreads();
    int woff = 0;
    #pragma unroll
    for (int j = 0; j < 8; j++) if (j < w) woff += wsum[j];

    int excl = g_boff[b] + woff + inc - s;    // exclusive prefix of chunk
    if (base < n) {
        int p0 = excl, p1 = p0 + v.x, p2 = p1 + v.y, p3 = p2 + v.z;
        g_rowptr[base] = p0;  g_cursor[base] = p0;
        if (base + 1 < n) { g_rowptr[base + 1] = p1; g_cursor[base + 1] = p1; }
        if (base + 2 < n) { g_rowptr[base + 2] = p2; g_cursor[base + 2] = p2; }
        if (base + 3 < n) { g_rowptr[base + 3] = p3; g_cursor[base + 3] = p3; }
    }
}

// -------------------------------------------------------- CSR scatter + w
__global__ void k_scatter(const void* __restrict__ ei,
                          const float* __restrict__ cv, int E) {
    int e = blockIdx.x * blockDim.x + threadIdx.x;
    if (e >= E) return;
    int is64 = g_is64;
    int r = edge_at(ei, E, 0, e, is64);
    int c = edge_at(ei, E, 1, e, is64);
    float wv = g_deg[r] * cv[e] * g_deg[c];
    int pos = atomicAdd(&g_cursor[r], 1);
    g_cw[pos] = make_int2(c, __float_as_int(wv));
}

// ---------------------------------------------------------- dense GEMM
// Y[n, c] = sum_k X[n,k] * W[c,k].
// Block: 64 nodes, 256 threads (8 warps). Warp handles 8 nodes; lane handles
// cols lane + 32*j, j < HT. W tile loaded in k-chunks of 16 (stride 17 ->
// conflict-free). x tile reads are lane-invariant broadcasts.
template <int HT, int LAYER>
__global__ void k_gemm(const float* __restrict__ Xin,
                       const float* __restrict__ W, int N, int Hreal) {
    __shared__ float xs[64 * 128];
    __shared__ float ws[HT * 32 * 17];
    const float* X = (LAYER == 1) ? Xin : (const float*)g_h;
    float*       Y = (LAYER == 1) ? g_y1 : g_y2;

    int tid = threadIdx.x;
    int nb = blockIdx.x * 64;

    for (int i = tid; i < 64 * 128; i += 256) {
        int n = i >> 7;
        xs[i] = (nb + n < N) ? X[(size_t)nb * 128 + i] : 0.0f;
    }

    int lane = tid & 31, wid = tid >> 5;
    float acc[8][HT];
    #pragma unroll
    for (int i = 0; i < 8; i++)
        #pragma unroll
        for (int j = 0; j < HT; j++) acc[i][j] = 0.0f;

    for (int kb = 0; kb < 128; kb += 16) {
        __syncthreads();
        for (int i = tid; i < HT * 32 * 16; i += 256) {
            int hh = i >> 4, kk = i & 15;
            ws[hh * 17 + kk] = (hh < Hreal) ? W[(size_t)hh * 128 + kb + kk] : 0.0f;
        }
        __syncthreads();

        #pragma unroll
        for (int kk = 0; kk < 16; kk++) {
            float wf[HT];
            #pragma unroll
            for (int j = 0; j < HT; j++) wf[j] = ws[(lane + 32 * j) * 17 + kk];
            #pragma unroll
            for (int i = 0; i < 8; i++) {
                float xf = xs[(wid * 8 + i) * 128 + kb + kk];
                #pragma unroll
                for (int j = 0; j < HT; j++)
                    acc[i][j] = fmaf(xf, wf[j], acc[i][j]);
            }
        }
    }

    #pragma unroll
    for (int i = 0; i < 8; i++) {
        int n = nb + wid * 8 + i;
        if (n < N) {
            #pragma unroll
            for (int j = 0; j < HT; j++) {
                int c = lane + 32 * j;
                if (c < Hreal) Y[(size_t)n * Hreal + c] = acc[i][j];
            }
        }
    }
}

// ---------------------------------------- CSR SpMM, 128 feats, bias+relu
__global__ void k_spmm128(const float* __restrict__ bias, int N) {
    int wid = threadIdx.x >> 5, lane = threadIdx.x & 31;
    int r = blockIdx.x * 8 + wid;
    if (r >= N) return;
    const float4* feat = (const float4*)g_y1;
    int e0 = g_rowptr[r], e1 = g_rowptr[r + 1];
    float4 acc = make_float4(0.f, 0.f, 0.f, 0.f);
    for (int e = e0; e < e1; e++) {
        int2 cw = g_cw[e];
        float wv = __int_as_float(cw.y);
        float4 v = feat[(size_t)cw.x * 32 + lane];
        acc.x = fmaf(wv, v.x, acc.x);
        acc.y = fmaf(wv, v.y, acc.y);
        acc.z = fmaf(wv, v.z, acc.z);
        acc.w = fmaf(wv, v.w, acc.w);
    }
    float4 b = ((const float4*)bias)[lane];
    acc.x = fmaxf(acc.x + b.x, 0.f);
    acc.y = fmaxf(acc.y + b.y, 0.f);
    acc.z = fmaxf(acc.z + b.z, 0.f);
    acc.w = fmaxf(acc.w + b.w, 0.f);
    ((float4*)g_h)[(size_t)r * 32 + lane] = acc;
}

// -------------------------------------------- CSR SpMM, 40 feats, + bias
__global__ void k_spmm40(const float* __restrict__ bias,
                         float* __restrict__ out, int N) {
    int wid = threadIdx.x >> 5, lane = threadIdx.x & 31;
    int r = blockIdx.x * 8 + wid;
    if (r >= N) return;
    int e0 = g_rowptr[r], e1 = g_rowptr[r + 1];
    float a0 = 0.f, a1 = 0.f;
    for (int e = e0; e < e1; e++) {
        int2 cw = g_cw[e];
        float wv = __int_as_float(cw.y);
        const float* f = g_y2 + (size_t)cw.x * 40;
        a0 = fmaf(wv, f[lane], a0);
        if (lane < 8) a1 = fmaf(wv, f[32 + lane], a1);
    }
    out[(size_t)r * 40 + lane] = a0 + bias[lane];
    if (lane < 8) out[(size_t)r * 40 + 32 + lane] = a1 + bias[32 + lane];
}

// ----------------------------------------------------------------- host
extern "C" void kernel_launch(void* const* d_in, const int* in_sizes, int n_in,
                              void* d_out, int out_size) {
    const float* x  = (const float*)d_in[0];
    const void*  ei = d_in[1];                 // int32 or int64, detected
    const float* cv = (const float*)d_in[2];
    const float* W1 = (const float*)d_in[3];
    const float* b1 = (const float*)d_in[4];
    const float* W2 = (const float*)d_in[5];
    const float* b2 = (const float*)d_in[6];
    float* out = (float*)d_out;

    int N = in_sizes[0] / 128;
    int E = in_sizes[2];

    static cudaStream_t s1 = nullptr;
    static cudaEvent_t ev_fork = nullptr, ev_join = nullptr;
    if (s1 == nullptr) {
        cudaStreamCreateWithFlags(&s1, cudaStreamNonBlocking);
        cudaEventCreateWithFlags(&ev_fork, cudaEventDisableTiming);
        cudaEventCreateWithFlags(&ev_join, cudaEventDisableTiming);
    }

    int gn = (N + 255) / 256;
    int ge = (E + 255) / 256;
    int gb = (N + 63) / 64;
    int nbs = (N + SCAN_CHUNK - 1) / SCAN_CHUNK;

    // Fork: CSR build chain on s1, concurrent with GEMM1 on main stream.
    cudaEventRecord(ev_fork, 0);
    cudaStreamWaitEvent(s1, ev_fork, 0);

    k_zero     <<<gn, 256, 0, s1>>>(ei, E, N);
    k_deg_count<<<ge, 256, 0, s1>>>(ei, cv, E);
    k_scan1    <<<nbs, 256, 0, s1>>>(N);
    k_scan2    <<<1, 128, 0, s1>>>(nbs, N);
    k_scan3    <<<nbs, 256, 0, s1>>>(N);
    k_scatter  <<<ge, 256, 0, s1>>>(ei, cv, E);
    cudaEventRecord(ev_join, s1);

    // GEMM1 on main stream: y1 = x @ W1^T, 128 cols (independent of CSR).
    k_gemm<4, 1><<<gb, 256>>>(x, W1, N, 128);

    // Join: spmm128 needs both y1 and the CSR.
    cudaStreamWaitEvent(0, ev_join, 0);

    k_spmm128<<<(N + 7) / 8, 256>>>(b1, N);
    k_gemm<2, 2><<<gb, 256>>>(nullptr, W2, N, 40);
    k_spmm40<<<(N + 7) / 8, 256>>>(b2, out, N);
}